// round 11
// baseline (speedup 1.0000x reference)
#include <cuda_runtime.h>

// pose3d_future loss — warp-specialized producer/consumer (R8 structure).
// 1 block/SM, 16 warps: warp 15 = TMA-bulk producer feeding a 15-stage ring
// (15 x 13.44 KB smem), warps 0-14 = consumers, one slot each. Static
// contiguous chunk per block. R11 tweak: the two TMA copies per stage issue
// from two lanes in parallel (lane0 pose, lane1 est) to cut serial producer
// latency per stage.
// P: [B,3,21] f32, E: [B,2,21] f32, bl: [20], R: [3,3], C: [3,1], conn: [20,2] i64

#define NJ 21
#define NB 20
#define TILE 32
#define NWARPS 16
#define THREADS (NWARPS * 32)
#define NSTAGE 15
#define PROD_WARP 15
#define MAXBLK 1024

#define POSE_F 63
#define EST_F  42
#define POSE_B (POSE_F * 4)                 // 252
#define EST_B  (EST_F * 4)                  // 168
#define STAGE_POSE_B (TILE * POSE_B)        // 8064
#define STAGE_EST_B  (TILE * EST_B)         // 5376
#define STAGE_B (STAGE_POSE_B + STAGE_EST_B)// 13440

// smem byte layout
#define OFF_FULL  0                          // 15 x 8B mbarriers
#define OFF_EMPTY 120                        // 15 x 8B mbarriers
#define OFF_FLAG  240                        // 15 x 4B stage flags (0=stop, else cnt)
#define OFF_BL    304                        // 20 floats
#define OFF_CONN  384                        // 40 ints
#define OFF_STAGE 640                        // 15 stages x 13440 B
#define SMEM_BYTES (OFF_STAGE + NSTAGE * STAGE_B)

__device__ double g_partP[MAXBLK];
__device__ double g_partB[MAXBLK];
__device__ unsigned int g_ticket;

__device__ __forceinline__ void mbar_init(unsigned int mbar, unsigned int cnt) {
    asm volatile("mbarrier.init.shared.b64 [%0], %1;" :: "r"(mbar), "r"(cnt) : "memory");
}
__device__ __forceinline__ void mbar_arrive(unsigned int mbar) {
    asm volatile("mbarrier.arrive.shared.b64 _, [%0];" :: "r"(mbar) : "memory");
}
__device__ __forceinline__ void mbar_expect_tx(unsigned int mbar, unsigned int bytes) {
    asm volatile("mbarrier.arrive.expect_tx.shared.b64 _, [%0], %1;"
                 :: "r"(mbar), "r"(bytes) : "memory");
}
__device__ __forceinline__ void mbar_wait(unsigned int mbar, unsigned int parity) {
    asm volatile(
        "{\n\t"
        ".reg .pred P;\n\t"
        "WAIT_%=:\n\t"
        "mbarrier.try_wait.parity.acquire.cta.shared::cta.b64 P, [%0], %1, 0x989680;\n\t"
        "@P bra DONE_%=;\n\t"
        "bra WAIT_%=;\n\t"
        "DONE_%=:\n\t"
        "}"
        :: "r"(mbar), "r"(parity) : "memory");
}
__device__ __forceinline__ void tma_bulk_1d(unsigned int dst, const void* src,
                                            unsigned int bytes, unsigned int mbar) {
    asm volatile(
        "cp.async.bulk.shared::cluster.global.mbarrier::complete_tx::bytes "
        "[%0], [%1], %2, [%3];"
        :: "r"(dst), "l"(src), "r"(bytes), "r"(mbar) : "memory");
}

__global__ __launch_bounds__(THREADS) void k_loss(
    const float* __restrict__ pose,
    const float* __restrict__ est,
    const float* __restrict__ bl,
    const float* __restrict__ R,
    const float* __restrict__ C,
    const long long* __restrict__ conn,
    float* __restrict__ out,
    int n, int ntiles, int nblocks)
{
    extern __shared__ char smem[];
    unsigned int smemBase = (unsigned int)__cvta_generic_to_shared(smem);
    int*   smFlag = (int*)(smem + OFF_FLAG);
    float* smBl   = (float*)(smem + OFF_BL);
    int*   smConn = (int*)(smem + OFF_CONN);

    int tid  = threadIdx.x;
    int lane = tid & 31;
    int wid  = tid >> 5;

    if (tid < NB) {
        smBl[tid] = bl[tid];
        smConn[2 * tid]     = (int)conn[2 * tid];
        smConn[2 * tid + 1] = (int)conn[2 * tid + 1];
    }
    if (tid < NSTAGE) {
        mbar_init(smemBase + OFF_FULL  + tid * 8, 1);
        mbar_init(smemBase + OFF_EMPTY + tid * 8, 1);
    }
    __syncthreads();

    // M = K @ R^T
    const float f = 525.0f, cx = 320.0f, cy = 240.0f;
    float M00 = f*R[0] + cx*R[2];
    float M01 = f*R[3] + cx*R[5];
    float M02 = f*R[6] + cx*R[8];
    float M10 = f*R[1] + cy*R[2];
    float M11 = f*R[4] + cy*R[5];
    float M12 = f*R[7] + cy*R[8];
    float M20 = R[2], M21 = R[5], M22 = R[8];
    float Cx = C[0], Cy = C[1], Cz = C[2];

    // contiguous tile chunk for this block
    int base_t = ntiles / nblocks;
    int rem_t  = ntiles % nblocks;
    int chunkStart = blockIdx.x * base_t + min(blockIdx.x, rem_t);
    int chunkCnt   = base_t + (blockIdx.x < rem_t ? 1 : 0);

    double accP = 0.0, accB = 0.0;

    if (wid == PROD_WARP) {
        // ---------------- producer (lanes 0-1 issue in parallel) ----------
        int s = 0;
        for (; s < chunkCnt; s++) {
            int slot  = s % NSTAGE;
            int round = s / NSTAGE;
            unsigned int fullB  = smemBase + OFF_FULL  + slot * 8;
            unsigned int emptyB = smemBase + OFF_EMPTY + slot * 8;
            if (round > 0 && lane < 2) mbar_wait(emptyB, (round - 1) & 1);
            __syncwarp();

            int t   = chunkStart + s;
            int tb  = t * TILE;
            int cnt = min(TILE, n - tb);
            unsigned int dstP = smemBase + OFF_STAGE + slot * STAGE_B;
            unsigned int dstE = dstP + STAGE_POSE_B;
            const char* srcP = (const char*)pose + (size_t)tb * POSE_B;
            const char* srcE = (const char*)est  + (size_t)tb * EST_B;

            if (cnt == TILE) {
                if (lane == 0) {
                    smFlag[slot] = cnt;          // STS before expect/arrive
                    mbar_expect_tx(fullB, STAGE_B);
                    tma_bulk_1d(dstP, srcP, STAGE_POSE_B, fullB);
                } else if (lane == 1) {
                    tma_bulk_1d(dstE, srcE, STAGE_EST_B, fullB);
                }
            } else if (lane == 0) {
                // cold path: partial tile, scalar copy + plain arrive
                smFlag[slot] = cnt;
                float* dp = (float*)(smem + OFF_STAGE + slot * STAGE_B);
                float* de = dp + TILE * POSE_F;
                for (int i = 0; i < cnt * POSE_F; i++) dp[i] = ((const float*)srcP)[i];
                for (int i = 0; i < cnt * EST_F;  i++) de[i] = ((const float*)srcE)[i];
                mbar_arrive(fullB);
            }
            __syncwarp();
        }
        // stop every slot exactly once
        for (int k2 = 0; k2 < NSTAGE; k2++, s++) {
            int slot  = s % NSTAGE;
            int round = s / NSTAGE;
            unsigned int fullB  = smemBase + OFF_FULL  + slot * 8;
            unsigned int emptyB = smemBase + OFF_EMPTY + slot * 8;
            if (round > 0 && lane == 0) mbar_wait(emptyB, (round - 1) & 1);
            __syncwarp();
            if (lane == 0) {
                smFlag[slot] = 0;
                mbar_arrive(fullB);
            }
            __syncwarp();
        }
    } else {
        // ---------------- consumer: warp w owns slot w ----------------
        int slot = wid;
        unsigned int fullB  = smemBase + OFF_FULL  + slot * 8;
        unsigned int emptyB = smemBase + OFF_EMPTY + slot * 8;
        const float* stageP = (const float*)(smem + OFF_STAGE + slot * STAGE_B);
        const float* stageE = stageP + TILE * POSE_F;

        for (int i = 0; ; i++) {
            mbar_wait(fullB, i & 1);
            int cnt = smFlag[slot];
            if (cnt == 0) break;

            if (lane < cnt) {
                const float* P = stageP + lane * POSE_F;
                const float* E = stageE + lane * EST_F;

                float psum = 0.0f;
                #pragma unroll
                for (int j = 0; j < NJ; j++) {
                    float dx = P[j]        - Cx;
                    float dy = P[NJ + j]   - Cy;
                    float dz = P[2*NJ + j] - Cz;
                    float px = M00*dx + M01*dy + M02*dz;
                    float py = M10*dx + M11*dy + M12*dz;
                    float pz = M20*dx + M21*dy + M22*dz;
                    float inv = __fdividef(1.0f, pz);
                    float u = px * inv - E[j];
                    float v = py * inv - E[NJ + j];
                    psum += u*u + v*v;
                }

                float bsum = 0.0f;
                #pragma unroll
                for (int j = 0; j < NB; j++) {
                    int a = smConn[2*j];
                    int b = smConn[2*j + 1];
                    float dx = P[a]        - P[b];
                    float dy = P[NJ + a]   - P[NJ + b];
                    float dz = P[2*NJ + a] - P[2*NJ + b];
                    float sq = dx*dx + dy*dy + dz*dz;
                    float tt = smBl[j] - sq;
                    bsum += tt*tt;
                }

                accP += (double)psum;
                accB += (double)bsum;
            }
            __syncwarp();                    // all lanes done with the stage
            if (lane == 0) mbar_arrive(emptyB);
        }
    }

    // ---------------- block reduce ----------------
    #pragma unroll
    for (int o = 16; o > 0; o >>= 1) {
        accP += __shfl_down_sync(0xffffffffu, accP, o);
        accB += __shfl_down_sync(0xffffffffu, accB, o);
    }
    __shared__ double sP[NWARPS], sB[NWARPS];
    __shared__ bool isLast;
    if (lane == 0) { sP[wid] = accP; sB[wid] = accB; }
    __syncthreads();
    if (tid == 0) {
        double aP = 0.0, aB = 0.0;
        #pragma unroll
        for (int w = 0; w < NWARPS; w++) { aP += sP[w]; aB += sB[w]; }
        g_partP[blockIdx.x] = aP;
        g_partB[blockIdx.x] = aB;
        __threadfence();
        unsigned int tk = atomicAdd(&g_ticket, 1u);
        isLast = (tk == (unsigned int)(nblocks - 1));
    }
    __syncthreads();

    if (isLast) {
        double aP = 0.0, aB = 0.0;
        for (int i = tid; i < nblocks; i += THREADS) {
            aP += g_partP[i];
            aB += g_partB[i];
        }
        #pragma unroll
        for (int o = 16; o > 0; o >>= 1) {
            aP += __shfl_down_sync(0xffffffffu, aP, o);
            aB += __shfl_down_sync(0xffffffffu, aB, o);
        }
        if (lane == 0) { sP[wid] = aP; sB[wid] = aB; }
        __syncthreads();
        if (tid == 0) {
            aP = 0.0; aB = 0.0;
            #pragma unroll
            for (int w = 0; w < NWARPS; w++) { aP += sP[w]; aB += sB[w]; }
            double invB = 1.0 / (double)n;
            double proj = aP * invB / (2.0 * NJ);
            double bone = aB * invB / (double)NB;
            out[0] = (float)(0.33 * proj + 0.5 * bone);
            g_ticket = 0;   // reset for next graph replay
        }
    }
}

extern "C" void kernel_launch(void* const* d_in, const int* in_sizes, int n_in,
                              void* d_out, int out_size) {
    const float*     pose = (const float*)d_in[0];
    const float*     est  = (const float*)d_in[1];
    const float*     bl   = (const float*)d_in[2];
    const float*     R    = (const float*)d_in[3];
    const float*     C    = (const float*)d_in[4];
    const long long* conn = (const long long*)d_in[5];
    float* out = (float*)d_out;

    int n = in_sizes[0] / (3 * NJ);
    int ntiles = (n + TILE - 1) / TILE;
    int blocks = 148;                    // 1 block/SM (~202 KB smem)
    if (blocks > ntiles) blocks = ntiles;

    cudaFuncSetAttribute(k_loss, cudaFuncAttributeMaxDynamicSharedMemorySize,
                         SMEM_BYTES);
    k_loss<<<blocks, THREADS, SMEM_BYTES>>>(pose, est, bl, R, C, conn, out,
                                            n, ntiles, blocks);
}

// round 12
// speedup vs baseline: 1.0358x; 1.0358x over previous
#include <cuda_runtime.h>

// pose3d_future loss — warp-specialized producer/consumer (R8 structure,
// ring deepened 15 -> 16 slots). 1 block/SM, 17 warps: warp 16 = TMA-bulk
// producer feeding a 16-stage ring (16 x 13.44 KB smem), warps 0-15 =
// consumers, one slot each. Static contiguous chunk per block.
// P: [B,3,21] f32, E: [B,2,21] f32, bl: [20], R: [3,3], C: [3,1], conn: [20,2] i64

#define NJ 21
#define NB 20
#define TILE 32
#define NWARPS 17
#define THREADS (NWARPS * 32)
#define NSTAGE 16
#define PROD_WARP 16
#define MAXBLK 1024

#define POSE_F 63
#define EST_F  42
#define POSE_B (POSE_F * 4)                 // 252
#define EST_B  (EST_F * 4)                  // 168
#define STAGE_POSE_B (TILE * POSE_B)        // 8064
#define STAGE_EST_B  (TILE * EST_B)         // 5376
#define STAGE_B (STAGE_POSE_B + STAGE_EST_B)// 13440

// smem byte layout
#define OFF_FULL  0                          // 16 x 8B mbarriers
#define OFF_EMPTY 128                        // 16 x 8B mbarriers
#define OFF_FLAG  256                        // 16 x 4B stage flags (0=stop, else cnt)
#define OFF_BL    320                        // 20 floats
#define OFF_CONN  400                        // 40 ints
#define OFF_STAGE 640                        // 16 stages x 13440 B
#define SMEM_BYTES (OFF_STAGE + NSTAGE * STAGE_B)   // 215680 (~210.6 KB)

__device__ double g_partP[MAXBLK];
__device__ double g_partB[MAXBLK];
__device__ unsigned int g_ticket;

__device__ __forceinline__ void mbar_init(unsigned int mbar, unsigned int cnt) {
    asm volatile("mbarrier.init.shared.b64 [%0], %1;" :: "r"(mbar), "r"(cnt) : "memory");
}
__device__ __forceinline__ void mbar_arrive(unsigned int mbar) {
    asm volatile("mbarrier.arrive.shared.b64 _, [%0];" :: "r"(mbar) : "memory");
}
__device__ __forceinline__ void mbar_expect_tx(unsigned int mbar, unsigned int bytes) {
    asm volatile("mbarrier.arrive.expect_tx.shared.b64 _, [%0], %1;"
                 :: "r"(mbar), "r"(bytes) : "memory");
}
__device__ __forceinline__ void mbar_wait(unsigned int mbar, unsigned int parity) {
    asm volatile(
        "{\n\t"
        ".reg .pred P;\n\t"
        "WAIT_%=:\n\t"
        "mbarrier.try_wait.parity.acquire.cta.shared::cta.b64 P, [%0], %1, 0x989680;\n\t"
        "@P bra DONE_%=;\n\t"
        "bra WAIT_%=;\n\t"
        "DONE_%=:\n\t"
        "}"
        :: "r"(mbar), "r"(parity) : "memory");
}
__device__ __forceinline__ void tma_bulk_1d(unsigned int dst, const void* src,
                                            unsigned int bytes, unsigned int mbar) {
    asm volatile(
        "cp.async.bulk.shared::cluster.global.mbarrier::complete_tx::bytes "
        "[%0], [%1], %2, [%3];"
        :: "r"(dst), "l"(src), "r"(bytes), "r"(mbar) : "memory");
}

__global__ __launch_bounds__(THREADS) void k_loss(
    const float* __restrict__ pose,
    const float* __restrict__ est,
    const float* __restrict__ bl,
    const float* __restrict__ R,
    const float* __restrict__ C,
    const long long* __restrict__ conn,
    float* __restrict__ out,
    int n, int ntiles, int nblocks)
{
    extern __shared__ char smem[];
    unsigned int smemBase = (unsigned int)__cvta_generic_to_shared(smem);
    int*   smFlag = (int*)(smem + OFF_FLAG);
    float* smBl   = (float*)(smem + OFF_BL);
    int*   smConn = (int*)(smem + OFF_CONN);

    int tid  = threadIdx.x;
    int lane = tid & 31;
    int wid  = tid >> 5;

    if (tid < NB) {
        smBl[tid] = bl[tid];
        smConn[2 * tid]     = (int)conn[2 * tid];
        smConn[2 * tid + 1] = (int)conn[2 * tid + 1];
    }
    if (tid < NSTAGE) {
        mbar_init(smemBase + OFF_FULL  + tid * 8, 1);
        mbar_init(smemBase + OFF_EMPTY + tid * 8, 1);
    }
    __syncthreads();

    // M = K @ R^T
    const float f = 525.0f, cx = 320.0f, cy = 240.0f;
    float M00 = f*R[0] + cx*R[2];
    float M01 = f*R[3] + cx*R[5];
    float M02 = f*R[6] + cx*R[8];
    float M10 = f*R[1] + cy*R[2];
    float M11 = f*R[4] + cy*R[5];
    float M12 = f*R[7] + cy*R[8];
    float M20 = R[2], M21 = R[5], M22 = R[8];
    float Cx = C[0], Cy = C[1], Cz = C[2];

    // contiguous tile chunk for this block
    int base_t = ntiles / nblocks;
    int rem_t  = ntiles % nblocks;
    int chunkStart = blockIdx.x * base_t + min(blockIdx.x, rem_t);
    int chunkCnt   = base_t + (blockIdx.x < rem_t ? 1 : 0);

    double accP = 0.0, accB = 0.0;

    if (wid == PROD_WARP) {
        // ---------------- producer (single lane) ----------------
        if (lane == 0) {
            int s = 0;
            for (; s < chunkCnt; s++) {
                int slot  = s % NSTAGE;
                int round = s / NSTAGE;
                unsigned int fullB  = smemBase + OFF_FULL  + slot * 8;
                unsigned int emptyB = smemBase + OFF_EMPTY + slot * 8;
                if (round > 0) mbar_wait(emptyB, (round - 1) & 1);

                int t   = chunkStart + s;
                int tb  = t * TILE;
                int cnt = min(TILE, n - tb);
                unsigned int dstP = smemBase + OFF_STAGE + slot * STAGE_B;
                unsigned int dstE = dstP + STAGE_POSE_B;
                const char* srcP = (const char*)pose + (size_t)tb * POSE_B;
                const char* srcE = (const char*)est  + (size_t)tb * EST_B;

                smFlag[slot] = cnt;          // STS before release-arrive
                if (cnt == TILE) {
                    mbar_expect_tx(fullB, STAGE_B);
                    tma_bulk_1d(dstP, srcP, STAGE_POSE_B, fullB);
                    tma_bulk_1d(dstE, srcE, STAGE_EST_B,  fullB);
                } else {
                    // cold path: partial tile, scalar copy + plain arrive
                    float* dp = (float*)(smem + OFF_STAGE + slot * STAGE_B);
                    float* de = dp + TILE * POSE_F;
                    for (int i = 0; i < cnt * POSE_F; i++) dp[i] = ((const float*)srcP)[i];
                    for (int i = 0; i < cnt * EST_F;  i++) de[i] = ((const float*)srcE)[i];
                    mbar_arrive(fullB);
                }
            }
            // stop every slot exactly once
            for (int k2 = 0; k2 < NSTAGE; k2++, s++) {
                int slot  = s % NSTAGE;
                int round = s / NSTAGE;
                unsigned int fullB  = smemBase + OFF_FULL  + slot * 8;
                unsigned int emptyB = smemBase + OFF_EMPTY + slot * 8;
                if (round > 0) mbar_wait(emptyB, (round - 1) & 1);
                smFlag[slot] = 0;
                mbar_arrive(fullB);
            }
        }
    } else {
        // ---------------- consumer: warp w owns slot w ----------------
        int slot = wid;
        unsigned int fullB  = smemBase + OFF_FULL  + slot * 8;
        unsigned int emptyB = smemBase + OFF_EMPTY + slot * 8;
        const float* stageP = (const float*)(smem + OFF_STAGE + slot * STAGE_B);
        const float* stageE = stageP + TILE * POSE_F;

        for (int i = 0; ; i++) {
            mbar_wait(fullB, i & 1);
            int cnt = smFlag[slot];
            if (cnt == 0) break;

            if (lane < cnt) {
                const float* P = stageP + lane * POSE_F;
                const float* E = stageE + lane * EST_F;

                float psum = 0.0f;
                #pragma unroll
                for (int j = 0; j < NJ; j++) {
                    float dx = P[j]        - Cx;
                    float dy = P[NJ + j]   - Cy;
                    float dz = P[2*NJ + j] - Cz;
                    float px = M00*dx + M01*dy + M02*dz;
                    float py = M10*dx + M11*dy + M12*dz;
                    float pz = M20*dx + M21*dy + M22*dz;
                    float inv = __fdividef(1.0f, pz);
                    float u = px * inv - E[j];
                    float v = py * inv - E[NJ + j];
                    psum += u*u + v*v;
                }

                float bsum = 0.0f;
                #pragma unroll
                for (int j = 0; j < NB; j++) {
                    int a = smConn[2*j];
                    int b = smConn[2*j + 1];
                    float dx = P[a]        - P[b];
                    float dy = P[NJ + a]   - P[NJ + b];
                    float dz = P[2*NJ + a] - P[2*NJ + b];
                    float sq = dx*dx + dy*dy + dz*dz;
                    float tt = smBl[j] - sq;
                    bsum += tt*tt;
                }

                accP += (double)psum;
                accB += (double)bsum;
            }
            __syncwarp();                    // all lanes done with the stage
            if (lane == 0) mbar_arrive(emptyB);
        }
    }

    // ---------------- block reduce ----------------
    #pragma unroll
    for (int o = 16; o > 0; o >>= 1) {
        accP += __shfl_down_sync(0xffffffffu, accP, o);
        accB += __shfl_down_sync(0xffffffffu, accB, o);
    }
    __shared__ double sP[NWARPS], sB[NWARPS];
    __shared__ bool isLast;
    if (lane == 0) { sP[wid] = accP; sB[wid] = accB; }
    __syncthreads();
    if (tid == 0) {
        double aP = 0.0, aB = 0.0;
        #pragma unroll
        for (int w = 0; w < NWARPS; w++) { aP += sP[w]; aB += sB[w]; }
        g_partP[blockIdx.x] = aP;
        g_partB[blockIdx.x] = aB;
        __threadfence();
        unsigned int tk = atomicAdd(&g_ticket, 1u);
        isLast = (tk == (unsigned int)(nblocks - 1));
    }
    __syncthreads();

    if (isLast) {
        double aP = 0.0, aB = 0.0;
        for (int i = tid; i < nblocks; i += THREADS) {
            aP += g_partP[i];
            aB += g_partB[i];
        }
        #pragma unroll
        for (int o = 16; o > 0; o >>= 1) {
            aP += __shfl_down_sync(0xffffffffu, aP, o);
            aB += __shfl_down_sync(0xffffffffu, aB, o);
        }
        if (lane == 0) { sP[wid] = aP; sB[wid] = aB; }
        __syncthreads();
        if (tid == 0) {
            aP = 0.0; aB = 0.0;
            #pragma unroll
            for (int w = 0; w < NWARPS; w++) { aP += sP[w]; aB += sB[w]; }
            double invB = 1.0 / (double)n;
            double proj = aP * invB / (2.0 * NJ);
            double bone = aB * invB / (double)NB;
            out[0] = (float)(0.33 * proj + 0.5 * bone);
            g_ticket = 0;   // reset for next graph replay
        }
    }
}

extern "C" void kernel_launch(void* const* d_in, const int* in_sizes, int n_in,
                              void* d_out, int out_size) {
    const float*     pose = (const float*)d_in[0];
    const float*     est  = (const float*)d_in[1];
    const float*     bl   = (const float*)d_in[2];
    const float*     R    = (const float*)d_in[3];
    const float*     C    = (const float*)d_in[4];
    const long long* conn = (const long long*)d_in[5];
    float* out = (float*)d_out;

    int n = in_sizes[0] / (3 * NJ);
    int ntiles = (n + TILE - 1) / TILE;
    int blocks = 148;                    // 1 block/SM (~210.6 KB smem)
    if (blocks > ntiles) blocks = ntiles;

    cudaFuncSetAttribute(k_loss, cudaFuncAttributeMaxDynamicSharedMemorySize,
                         SMEM_BYTES);
    k_loss<<<blocks, THREADS, SMEM_BYTES>>>(pose, est, bl, R, C, conn, out,
                                            n, ntiles, blocks);
}

// round 13
// speedup vs baseline: 1.0886x; 1.0510x over previous
#include <cuda_runtime.h>

// pose3d_future loss — warp-specialized producer/consumer (R8 structure,
// protocol slimmed). 1 block/SM, 16 warps: warp 15 = single-lane TMA-bulk
// producer feeding a 15-stage ring (15 x 13.44 KB smem), warps 0-14 =
// consumers, one slot each. Static contiguous chunk per block. No stage
// flags / stop stages: every warp computes its exact stage count up front
// (n is a multiple of TILE in the hot path; partial tail handled inline).
// P: [B,3,21] f32, E: [B,2,21] f32, bl: [20], R: [3,3], C: [3,1], conn: [20,2] i64

#define NJ 21
#define NB 20
#define TILE 32
#define NWARPS 16
#define THREADS (NWARPS * 32)
#define NSTAGE 15
#define PROD_WARP 15
#define MAXBLK 1024

#define POSE_F 63
#define EST_F  42
#define POSE_B (POSE_F * 4)                 // 252
#define EST_B  (EST_F * 4)                  // 168
#define STAGE_POSE_B (TILE * POSE_B)        // 8064
#define STAGE_EST_B  (TILE * EST_B)         // 5376
#define STAGE_B (STAGE_POSE_B + STAGE_EST_B)// 13440

// smem byte layout
#define OFF_FULL  0                          // 15 x 8B mbarriers
#define OFF_EMPTY 120                        // 15 x 8B mbarriers
#define OFF_BL    240                        // 20 floats
#define OFF_CONN  320                        // 40 ints
#define OFF_STAGE 512                        // 15 stages x 13440 B
#define SMEM_BYTES (OFF_STAGE + NSTAGE * STAGE_B)   // 202112

__device__ double g_partP[MAXBLK];
__device__ double g_partB[MAXBLK];
__device__ unsigned int g_ticket;

__device__ __forceinline__ void mbar_init(unsigned int mbar, unsigned int cnt) {
    asm volatile("mbarrier.init.shared.b64 [%0], %1;" :: "r"(mbar), "r"(cnt) : "memory");
}
__device__ __forceinline__ void mbar_arrive(unsigned int mbar) {
    asm volatile("mbarrier.arrive.shared.b64 _, [%0];" :: "r"(mbar) : "memory");
}
__device__ __forceinline__ void mbar_expect_tx(unsigned int mbar, unsigned int bytes) {
    asm volatile("mbarrier.arrive.expect_tx.shared.b64 _, [%0], %1;"
                 :: "r"(mbar), "r"(bytes) : "memory");
}
__device__ __forceinline__ void mbar_wait(unsigned int mbar, unsigned int parity) {
    asm volatile(
        "{\n\t"
        ".reg .pred P;\n\t"
        "WAIT_%=:\n\t"
        "mbarrier.try_wait.parity.acquire.cta.shared::cta.b64 P, [%0], %1, 0x989680;\n\t"
        "@P bra DONE_%=;\n\t"
        "bra WAIT_%=;\n\t"
        "DONE_%=:\n\t"
        "}"
        :: "r"(mbar), "r"(parity) : "memory");
}
__device__ __forceinline__ void tma_bulk_1d(unsigned int dst, const void* src,
                                            unsigned int bytes, unsigned int mbar) {
    asm volatile(
        "cp.async.bulk.shared::cluster.global.mbarrier::complete_tx::bytes "
        "[%0], [%1], %2, [%3];"
        :: "r"(dst), "l"(src), "r"(bytes), "r"(mbar) : "memory");
}

__global__ __launch_bounds__(THREADS) void k_loss(
    const float* __restrict__ pose,
    const float* __restrict__ est,
    const float* __restrict__ bl,
    const float* __restrict__ R,
    const float* __restrict__ C,
    const long long* __restrict__ conn,
    float* __restrict__ out,
    int n, int ntiles, int nblocks)
{
    extern __shared__ char smem[];
    unsigned int smemBase = (unsigned int)__cvta_generic_to_shared(smem);
    float* smBl   = (float*)(smem + OFF_BL);
    int*   smConn = (int*)(smem + OFF_CONN);

    int tid  = threadIdx.x;
    int lane = tid & 31;
    int wid  = tid >> 5;

    if (tid < NB) {
        smBl[tid] = bl[tid];
        smConn[2 * tid]     = (int)conn[2 * tid];
        smConn[2 * tid + 1] = (int)conn[2 * tid + 1];
    }
    if (tid < NSTAGE) {
        mbar_init(smemBase + OFF_FULL  + tid * 8, 1);
        mbar_init(smemBase + OFF_EMPTY + tid * 8, 1);
    }
    __syncthreads();

    // M = K @ R^T
    const float f = 525.0f, cx = 320.0f, cy = 240.0f;
    float M00 = f*R[0] + cx*R[2];
    float M01 = f*R[3] + cx*R[5];
    float M02 = f*R[6] + cx*R[8];
    float M10 = f*R[1] + cy*R[2];
    float M11 = f*R[4] + cy*R[5];
    float M12 = f*R[7] + cy*R[8];
    float M20 = R[2], M21 = R[5], M22 = R[8];
    float Cx = C[0], Cy = C[1], Cz = C[2];

    // contiguous tile chunk for this block
    int base_t = ntiles / nblocks;
    int rem_t  = ntiles % nblocks;
    int chunkStart = blockIdx.x * base_t + min(blockIdx.x, rem_t);
    int chunkCnt   = base_t + (blockIdx.x < rem_t ? 1 : 0);

    double accP = 0.0, accB = 0.0;

    if (wid == PROD_WARP) {
        // ---------------- producer (single lane) ----------------
        if (lane == 0) {
            for (int s = 0; s < chunkCnt; s++) {
                int slot  = s % NSTAGE;
                int round = s / NSTAGE;
                unsigned int fullB  = smemBase + OFF_FULL  + slot * 8;
                unsigned int emptyB = smemBase + OFF_EMPTY + slot * 8;
                if (round > 0) mbar_wait(emptyB, (round - 1) & 1);

                int t   = chunkStart + s;
                int tb  = t * TILE;
                int cnt = min(TILE, n - tb);
                unsigned int dstP = smemBase + OFF_STAGE + slot * STAGE_B;
                unsigned int dstE = dstP + STAGE_POSE_B;
                const char* srcP = (const char*)pose + (size_t)tb * POSE_B;
                const char* srcE = (const char*)est  + (size_t)tb * EST_B;

                if (cnt == TILE) {
                    mbar_expect_tx(fullB, STAGE_B);
                    tma_bulk_1d(dstP, srcP, STAGE_POSE_B, fullB);
                    tma_bulk_1d(dstE, srcE, STAGE_EST_B,  fullB);
                } else {
                    // cold path: partial tail tile, scalar copy + plain arrive
                    float* dp = (float*)(smem + OFF_STAGE + slot * STAGE_B);
                    float* de = dp + TILE * POSE_F;
                    for (int i = 0; i < cnt * POSE_F; i++) dp[i] = ((const float*)srcP)[i];
                    for (int i = 0; i < cnt * EST_F;  i++) de[i] = ((const float*)srcE)[i];
                    mbar_arrive(fullB);
                }
            }
        }
    } else {
        // ---------------- consumer: warp w owns slot w ----------------
        int slot = wid;
        unsigned int fullB  = smemBase + OFF_FULL  + slot * 8;
        unsigned int emptyB = smemBase + OFF_EMPTY + slot * 8;
        const float* stageP = (const float*)(smem + OFF_STAGE + slot * STAGE_B);
        const float* stageE = stageP + TILE * POSE_F;

        int i = 0;
        for (int s = wid; s < chunkCnt; s += NSTAGE, i++) {
            mbar_wait(fullB, i & 1);

            int t   = chunkStart + s;
            int tb  = t * TILE;
            int cnt = min(TILE, n - tb);

            if (lane < cnt) {
                const float* P = stageP + lane * POSE_F;
                const float* E = stageE + lane * EST_F;

                float psum = 0.0f;
                #pragma unroll
                for (int j = 0; j < NJ; j++) {
                    float dx = P[j]        - Cx;
                    float dy = P[NJ + j]   - Cy;
                    float dz = P[2*NJ + j] - Cz;
                    float px = M00*dx + M01*dy + M02*dz;
                    float py = M10*dx + M11*dy + M12*dz;
                    float pz = M20*dx + M21*dy + M22*dz;
                    float inv = __fdividef(1.0f, pz);
                    float u = px * inv - E[j];
                    float v = py * inv - E[NJ + j];
                    psum += u*u + v*v;
                }

                float bsum = 0.0f;
                #pragma unroll
                for (int j = 0; j < NB; j++) {
                    int a = smConn[2*j];
                    int b = smConn[2*j + 1];
                    float dx = P[a]        - P[b];
                    float dy = P[NJ + a]   - P[NJ + b];
                    float dz = P[2*NJ + a] - P[2*NJ + b];
                    float sq = dx*dx + dy*dy + dz*dz;
                    float tt = smBl[j] - sq;
                    bsum += tt*tt;
                }

                accP += (double)psum;
                accB += (double)bsum;
            }
            __syncwarp();                    // all lanes done with the stage
            if (lane == 0) mbar_arrive(emptyB);
        }
    }

    // ---------------- block reduce ----------------
    #pragma unroll
    for (int o = 16; o > 0; o >>= 1) {
        accP += __shfl_down_sync(0xffffffffu, accP, o);
        accB += __shfl_down_sync(0xffffffffu, accB, o);
    }
    __shared__ double sP[NWARPS], sB[NWARPS];
    __shared__ bool isLast;
    if (lane == 0) { sP[wid] = accP; sB[wid] = accB; }
    __syncthreads();
    if (tid == 0) {
        double aP = 0.0, aB = 0.0;
        #pragma unroll
        for (int w = 0; w < NWARPS; w++) { aP += sP[w]; aB += sB[w]; }
        g_partP[blockIdx.x] = aP;
        g_partB[blockIdx.x] = aB;
        __threadfence();
        unsigned int tk = atomicAdd(&g_ticket, 1u);
        isLast = (tk == (unsigned int)(nblocks - 1));
    }
    __syncthreads();

    if (isLast) {
        double aP = 0.0, aB = 0.0;
        for (int i = tid; i < nblocks; i += THREADS) {
            aP += g_partP[i];
            aB += g_partB[i];
        }
        #pragma unroll
        for (int o = 16; o > 0; o >>= 1) {
            aP += __shfl_down_sync(0xffffffffu, aP, o);
            aB += __shfl_down_sync(0xffffffffu, aB, o);
        }
        if (lane == 0) { sP[wid] = aP; sB[wid] = aB; }
        __syncthreads();
        if (tid == 0) {
            aP = 0.0; aB = 0.0;
            #pragma unroll
            for (int w = 0; w < NWARPS; w++) { aP += sP[w]; aB += sB[w]; }
            double invB = 1.0 / (double)n;
            double proj = aP * invB / (2.0 * NJ);
            double bone = aB * invB / (double)NB;
            out[0] = (float)(0.33 * proj + 0.5 * bone);
            g_ticket = 0;   // reset for next graph replay
        }
    }
}

extern "C" void kernel_launch(void* const* d_in, const int* in_sizes, int n_in,
                              void* d_out, int out_size) {
    const float*     pose = (const float*)d_in[0];
    const float*     est  = (const float*)d_in[1];
    const float*     bl   = (const float*)d_in[2];
    const float*     R    = (const float*)d_in[3];
    const float*     C    = (const float*)d_in[4];
    const long long* conn = (const long long*)d_in[5];
    float* out = (float*)d_out;

    int n = in_sizes[0] / (3 * NJ);
    int ntiles = (n + TILE - 1) / TILE;
    int blocks = 148;                    // 1 block/SM (~202 KB smem)
    if (blocks > ntiles) blocks = ntiles;

    cudaFuncSetAttribute(k_loss, cudaFuncAttributeMaxDynamicSharedMemorySize,
                         SMEM_BYTES);
    k_loss<<<blocks, THREADS, SMEM_BYTES>>>(pose, est, bl, R, C, conn, out,
                                            n, ntiles, blocks);
}